// round 10
// baseline (speedup 1.0000x reference)
#include <cuda_runtime.h>
#include <cstdint>

#define SQ   4096
#define EMBD 768
#define NHD  12
#define DHD  64

// Scratch (allocation-free: __device__ globals)
static __device__ float g_Q[SQ * EMBD];
static __device__ float g_K[SQ * EMBD];
static __device__ float g_V[SQ * EMBD];
static __device__ float g_AO[SQ * EMBD];
static __device__ float g_X[SQ * EMBD];          // tf32-rounded x
static __device__ float g_Wr[4 * EMBD * EMBD];   // tf32-rounded Wq,Wk,Wv,Wo

__device__ __forceinline__ float tf32r(float x) {
    float y;
    asm("cvt.rna.tf32.f32 %0, %1;" : "=f"(y) : "f"(x));
    return y;
}
__device__ __forceinline__ float ex2f(float x) {
    float y;
    asm("ex2.approx.ftz.f32 %0, %1;" : "=f"(y) : "f"(x));
    return y;
}
// D += A(16x8, row) * B(8x8, col), tf32 inputs / f32 accumulate
__device__ __forceinline__ void mma8(float* c, const float* a, const float* b) {
    asm volatile(
        "mma.sync.aligned.m16n8k8.row.col.f32.tf32.tf32.f32 "
        "{%0,%1,%2,%3}, {%4,%5,%6,%7}, {%8,%9}, {%0,%1,%2,%3};\n"
        : "+f"(c[0]), "+f"(c[1]), "+f"(c[2]), "+f"(c[3])
        : "r"(__float_as_uint(a[0])), "r"(__float_as_uint(a[1])),
          "r"(__float_as_uint(a[2])), "r"(__float_as_uint(a[3])),
          "r"(__float_as_uint(b[0])), "r"(__float_as_uint(b[1])));
}
__device__ __forceinline__ void cp16(uint32_t dst, const void* src) {
    asm volatile("cp.async.cg.shared.global [%0], [%1], 16;\n"
                 :: "r"(dst), "l"(src));
}

// ---------------------------------------------------------------------------
// Pre-round pass: tf32-round x and the four weight matrices once.
// ---------------------------------------------------------------------------
struct RArgs {
    const float* src[5];
    float* dst[5];
    int n4[5];   // element count / 4
};

__global__ void __launch_bounds__(256) round_pass(RArgs ra)
{
#pragma unroll
    for (int s = 0; s < 5; s++) {
        const float4* src = (const float4*)ra.src[s];
        float4* dst = (float4*)ra.dst[s];
        int n4 = ra.n4[s];
        for (int i = blockIdx.x * blockDim.x + threadIdx.x; i < n4;
             i += gridDim.x * blockDim.x) {
            float4 v = src[i];
            dst[i] = make_float4(tf32r(v.x), tf32r(v.y), tf32r(v.z), tf32r(v.w));
        }
    }
}

// ---------------------------------------------------------------------------
// GEMM v3: C[M,N] = A[M,K]*W[N,K]^T + bias. Inputs pre-rounded to tf32.
// CTA 128x128, 128 threads (4 warps, 2x2), warp tile 64x64, BK=32,
// cp.async double-buffered smem (2*(128*36)*2 floats = 73728 B dynamic).
// smem stride 36 -> fragment bank index 4g+cc, conflict-free.
// ---------------------------------------------------------------------------
#define GBK 32
#define GT  4608   // 128*36 floats per buffer

__device__ __forceinline__ void gemm3_body(
    const float* __restrict__ A, const float* __restrict__ W,
    const float* __restrict__ bias, float* __restrict__ C,
    int M, int N, int K, int round_out)
{
    extern __shared__ float gsm[];
    const uint32_t sb = (uint32_t)__cvta_generic_to_shared(gsm);
    const int t = threadIdx.x, lane = t & 31, wid = t >> 5;
    const int g = lane >> 2, cc = lane & 3;
    const int m0 = blockIdx.y * 128, n0 = blockIdx.x * 128;
    const int wm = (wid >> 1) * 64, wn = (wid & 1) * 64;

    const float* Arow = A + (size_t)(m0 + t) * K;
    const float* Wrow = W + (size_t)(n0 + t) * K;
    const uint32_t asb = sb + t * 144;                 // As row t (buffer 0)
    const uint32_t bsb = sb + (2 * GT) * 4 + t * 144;  // Bs row t (buffer 0)

#define G_ISSUE(kt)                                                     \
    do {                                                                \
        int _b = (kt) & 1;                                              \
        uint32_t _ad = asb + _b * (GT * 4);                             \
        uint32_t _bd = bsb + _b * (GT * 4);                             \
        const float* _as = Arow + (kt) * GBK;                           \
        const float* _ws = Wrow + (kt) * GBK;                           \
        _Pragma("unroll")                                               \
        for (int _i = 0; _i < 8; _i++) {                                \
            cp16(_ad + _i * 16, _as + _i * 4);                          \
            cp16(_bd + _i * 16, _ws + _i * 4);                          \
        }                                                               \
    } while (0)

    G_ISSUE(0);
    asm volatile("cp.async.commit_group;\n");

    float acc[4][8][4];
#pragma unroll
    for (int a = 0; a < 4; a++)
#pragma unroll
        for (int b = 0; b < 8; b++)
#pragma unroll
            for (int c = 0; c < 4; c++) acc[a][b][c] = 0.f;

    const int NKT = K / GBK;   // 24
    for (int kt = 0; kt < NKT; kt++) {
        __syncthreads();                   // prev compute done; buffer free
        if (kt + 1 < NKT) {
            G_ISSUE(kt + 1);
            asm volatile("cp.async.commit_group;\n");
            asm volatile("cp.async.wait_group 1;\n");
        } else {
            asm volatile("cp.async.wait_group 0;\n");
        }
        __syncthreads();                   // tile kt visible

        const float* As = gsm + (kt & 1) * GT;
        const float* Bs = gsm + 2 * GT + (kt & 1) * GT;

#pragma unroll
        for (int ks = 0; ks < 4; ks++) {
            float a[4][4], b[8][2];
#pragma unroll
            for (int tm = 0; tm < 4; tm++) {
                int r = wm + tm * 16 + g;
                a[tm][0] = As[r * 36 + ks * 8 + cc];
                a[tm][1] = As[(r + 8) * 36 + ks * 8 + cc];
                a[tm][2] = As[r * 36 + ks * 8 + cc + 4];
                a[tm][3] = As[(r + 8) * 36 + ks * 8 + cc + 4];
            }
#pragma unroll
            for (int tn = 0; tn < 8; tn++) {
                int n = wn + tn * 8 + g;
                b[tn][0] = Bs[n * 36 + ks * 8 + cc];
                b[tn][1] = Bs[n * 36 + ks * 8 + cc + 4];
            }
#pragma unroll
            for (int tm = 0; tm < 4; tm++)
#pragma unroll
                for (int tn = 0; tn < 8; tn++)
                    mma8(acc[tm][tn], a[tm], b[tn]);
        }
    }

#pragma unroll
    for (int tm = 0; tm < 4; tm++) {
        int r = m0 + wm + tm * 16 + g;
#pragma unroll
        for (int tn = 0; tn < 8; tn++) {
            int col = n0 + wn + tn * 8 + 2 * cc;
            float2 bv = *(const float2*)&bias[col];
            float2 r0, r1;
            r0.x = acc[tm][tn][0] + bv.x; r0.y = acc[tm][tn][1] + bv.y;
            r1.x = acc[tm][tn][2] + bv.x; r1.y = acc[tm][tn][3] + bv.y;
            if (round_out) {
                r0.x = tf32r(r0.x); r0.y = tf32r(r0.y);
                r1.x = tf32r(r1.x); r1.y = tf32r(r1.y);
            }
            *(float2*)&C[(size_t)r * N + col] = r0;
            *(float2*)&C[(size_t)(r + 8) * N + col] = r1;
        }
    }
#undef G_ISSUE
}

struct QKVArgs {
    const float* W[3];
    const float* b[3];
    float* C[3];
};

__global__ void __launch_bounds__(128) gemm_qkv3(
    const float* __restrict__ A, QKVArgs args, int M, int N, int K)
{
    int z = blockIdx.z;
    gemm3_body(A, args.W[z], args.b[z], args.C[z], M, N, K, 1);
}

__global__ void __launch_bounds__(128) gemm_out3(
    const float* __restrict__ A, const float* __restrict__ W,
    const float* __restrict__ bias, float* __restrict__ C,
    int M, int N, int K)
{
    gemm3_body(A, W, bias, C, M, N, K, 0);
}

// ---------------------------------------------------------------------------
// Flash attention (round-5 structure, proven): tf32 mma, flat softmax,
// P-in-registers, cp.async double-buffered K/V. Epilogue rounds AO to tf32
// for the output GEMM. Carveout attr set host-side for 2 CTAs/SM.
// smem floats: Qs 128*68 | K[2] 64*68 | V[2] 64*68 | mask[2] 64 = 104960 B
// ---------------------------------------------------------------------------
#define Q_OFF   0
#define K_OFF   8704
#define V_OFF   17408
#define M_OFF   26112
#define KV_SZ   4352

__global__ void __launch_bounds__(128) attn_tc3(const float* __restrict__ mask)
{
    extern __shared__ float sm[];
    float* Qs = sm + Q_OFF;
    const uint32_t sbase = (uint32_t)__cvta_generic_to_shared(sm);

    const int t = threadIdx.x, lane = t & 31, wid = t >> 5;
    const int g = lane >> 2, cc = lane & 3;
    const int h = blockIdx.y, q0 = blockIdx.x * 128;
    const int wbase = wid * 32;
    const int lr = t & 63, lc0 = (t >> 6) * 32;   // K/V loader: row, col-half

    // Stage Q tile [128][68] (already tf32-rounded by the QKV GEMM)
    {
        const float* qp = g_Q + (size_t)(q0 + t) * EMBD + h * DHD;
#pragma unroll
        for (int i = 0; i < 16; i++)
            *(float4*)&Qs[t * 68 + 4 * i] = *(const float4*)(qp + 4 * i);
    }

    const float* kbase = g_K + (size_t)lr * EMBD + h * DHD + lc0;
    const float* vbase = g_V + (size_t)lr * EMBD + h * DHD + lc0;
    const uint32_t kdst0 = sbase + (K_OFF + lr * 68 + lc0) * 4;
    const uint32_t vdst0 = sbase + (V_OFF + lr * 68 + lc0) * 4;

#define ISSUE_TILE(it)                                                        \
    do {                                                                      \
        int _c = (it) & 1;                                                    \
        const float* _ks = kbase + (size_t)(it) * 64 * EMBD;                  \
        const float* _vs = vbase + (size_t)(it) * 64 * EMBD;                  \
        uint32_t _kd = kdst0 + _c * (KV_SZ * 4);                              \
        uint32_t _vd = vdst0 + _c * (KV_SZ * 4);                              \
        _Pragma("unroll")                                                     \
        for (int _i = 0; _i < 8; _i++) {                                      \
            cp16(_kd + 16 * _i, _ks + 4 * _i);                                \
            cp16(_vd + 16 * _i, _vs + 4 * _i);                                \
        }                                                                     \
        if (t < 16)                                                           \
            cp16(sbase + (M_OFF + _c * 64 + t * 4) * 4,                       \
                 mask + (it) * 64 + t * 4);                                   \
    } while (0)

    ISSUE_TILE(0);
    asm volatile("cp.async.commit_group;\n");

    float O[2][8][4];
#pragma unroll
    for (int tm = 0; tm < 2; tm++)
#pragma unroll
        for (int tn = 0; tn < 8; tn++)
#pragma unroll
            for (int j = 0; j < 4; j++) O[tm][tn][j] = 0.f;
    float lacc[2][2] = {{0.f, 0.f}, {0.f, 0.f}};   // partial row sums

    const int NT = SQ / 64;   // 64 kv tiles
    for (int it = 0; it < NT; it++) {
        const int cur = it & 1;
        __syncthreads();                    // prev compute done; buf free
        if (it + 1 < NT) {
            ISSUE_TILE(it + 1);
            asm volatile("cp.async.commit_group;\n");
            asm volatile("cp.async.wait_group 1;\n");
        } else {
            asm volatile("cp.async.wait_group 0;\n");
        }
        __syncthreads();                    // tile `it` visible to all

        const float* Kc = sm + K_OFF + cur * KV_SZ;
        const float* Vc = sm + V_OFF + cur * KV_SZ;
        const float* Mc = sm + M_OFF + cur * 64;

        // ---- S = Q * K^T (2 row-blocks x 64 keys per warp) ----
        float S[2][8][4];
#pragma unroll
        for (int tm = 0; tm < 2; tm++)
#pragma unroll
            for (int tn = 0; tn < 8; tn++)
#pragma unroll
                for (int j = 0; j < 4; j++) S[tm][tn][j] = 0.f;

#pragma unroll
        for (int ks = 0; ks < 8; ks++) {
            float a0[4], a1[4];
            {
                int r0 = wbase + g, r1 = wbase + 16 + g;
                a0[0] = Qs[r0 * 68 + ks * 8 + cc];
                a0[1] = Qs[(r0 + 8) * 68 + ks * 8 + cc];
                a0[2] = Qs[r0 * 68 + ks * 8 + cc + 4];
                a0[3] = Qs[(r0 + 8) * 68 + ks * 8 + cc + 4];
                a1[0] = Qs[r1 * 68 + ks * 8 + cc];
                a1[1] = Qs[(r1 + 8) * 68 + ks * 8 + cc];
                a1[2] = Qs[r1 * 68 + ks * 8 + cc + 4];
                a1[3] = Qs[(r1 + 8) * 68 + ks * 8 + cc + 4];
            }
#pragma unroll
            for (int tn = 0; tn < 8; tn++) {
                float b[2];
                b[0] = Kc[(tn * 8 + g) * 68 + ks * 8 + cc];
                b[1] = Kc[(tn * 8 + g) * 68 + ks * 8 + cc + 4];
                mma8(S[0][tn], a0, b);   // b reused across row-blocks
                mma8(S[1][tn], a1, b);
            }
        }

        // ---- flat softmax numerator: P = exp2(S*SCL + mad); accumulate l ----
        const float SCL = 0.180336880466f;       // 0.125 * log2(e)
        float madx[8], mady[8];
#pragma unroll
        for (int tn = 0; tn < 8; tn++) {
            float2 mv = *(const float2*)&Mc[tn * 8 + 2 * cc];
            madx[tn] = (mv.x - 1.f) * 14426.950408f;  // -10000*log2e*(1-m)
            mady[tn] = (mv.y - 1.f) * 14426.950408f;
        }
#pragma unroll
        for (int tm = 0; tm < 2; tm++) {
#pragma unroll
            for (int tn = 0; tn < 8; tn++) {
                S[tm][tn][0] = ex2f(S[tm][tn][0] * SCL + madx[tn]);
                S[tm][tn][1] = ex2f(S[tm][tn][1] * SCL + mady[tn]);
                S[tm][tn][2] = ex2f(S[tm][tn][2] * SCL + madx[tn]);
                S[tm][tn][3] = ex2f(S[tm][tn][3] * SCL + mady[tn]);
                lacc[tm][0] += S[tm][tn][0] + S[tm][tn][1];
                lacc[tm][1] += S[tm][tn][2] + S[tm][tn][3];
            }
        }

        // ---- O += P * V  (P = S registers; V rows at physical keys 2cc,2cc+1)
#pragma unroll
        for (int ks = 0; ks < 8; ks++) {
            float a0[4], a1[4];
            a0[0] = tf32r(S[0][ks][0]); a0[1] = tf32r(S[0][ks][2]);
            a0[2] = tf32r(S[0][ks][1]); a0[3] = tf32r(S[0][ks][3]);
            a1[0] = tf32r(S[1][ks][0]); a1[1] = tf32r(S[1][ks][2]);
            a1[2] = tf32r(S[1][ks][1]); a1[3] = tf32r(S[1][ks][3]);
#pragma unroll
            for (int tn = 0; tn < 8; tn++) {
                float b[2];
                b[0] = Vc[(ks * 8 + 2 * cc) * 68 + tn * 8 + g];
                b[1] = Vc[(ks * 8 + 2 * cc + 1) * 68 + tn * 8 + g];
                mma8(O[0][tn], a0, b);
                mma8(O[1][tn], a1, b);
            }
        }
    }

    // epilogue: reduce row sums across the 4 cc-lanes, normalize, round, write.
#pragma unroll
    for (int tm = 0; tm < 2; tm++) {
#pragma unroll
        for (int half = 0; half < 2; half++) {
            lacc[tm][half] += __shfl_xor_sync(0xffffffffu, lacc[tm][half], 1);
            lacc[tm][half] += __shfl_xor_sync(0xffffffffu, lacc[tm][half], 2);
        }
    }
#pragma unroll
    for (int tm = 0; tm < 2; tm++) {
        float i0 = 1.f / lacc[tm][0], i1 = 1.f / lacc[tm][1];
        int r = q0 + wbase + tm * 16 + g;
#pragma unroll
        for (int tn = 0; tn < 8; tn++) {
            int col = h * DHD + tn * 8 + 2 * cc;
            float2 r0, r1;
            r0.x = tf32r(O[tm][tn][0] * i0); r0.y = tf32r(O[tm][tn][1] * i0);
            r1.x = tf32r(O[tm][tn][2] * i1); r1.y = tf32r(O[tm][tn][3] * i1);
            *(float2*)&g_AO[(size_t)r * EMBD + col] = r0;
            *(float2*)&g_AO[(size_t)(r + 8) * EMBD + col] = r1;
        }
    }
}

// ---------------------------------------------------------------------------
extern "C" void kernel_launch(void* const* d_in, const int* in_sizes, int n_in,
                              void* d_out, int out_size)
{
    const float* x    = (const float*)d_in[0];
    const float* mask = (const float*)d_in[1];
    float* out = (float*)d_out;

    float *Qp, *Kp, *Vp, *AOp, *Xp, *Wrp;
    cudaGetSymbolAddress((void**)&Qp,  g_Q);
    cudaGetSymbolAddress((void**)&Kp,  g_K);
    cudaGetSymbolAddress((void**)&Vp,  g_V);
    cudaGetSymbolAddress((void**)&AOp, g_AO);
    cudaGetSymbolAddress((void**)&Xp,  g_X);
    cudaGetSymbolAddress((void**)&Wrp, g_Wr);

    RArgs ra;
    ra.src[0] = x;                      ra.dst[0] = Xp;
    ra.src[1] = (const float*)d_in[2];  ra.dst[1] = Wrp + 0 * EMBD * EMBD;
    ra.src[2] = (const float*)d_in[4];  ra.dst[2] = Wrp + 1 * EMBD * EMBD;
    ra.src[3] = (const float*)d_in[6];  ra.dst[3] = Wrp + 2 * EMBD * EMBD;
    ra.src[4] = (const float*)d_in[8];  ra.dst[4] = Wrp + 3 * EMBD * EMBD;
    ra.n4[0] = SQ * EMBD / 4;
    ra.n4[1] = ra.n4[2] = ra.n4[3] = ra.n4[4] = EMBD * EMBD / 4;

    QKVArgs qkv;
    qkv.W[0] = Wrp + 0 * EMBD * EMBD; qkv.b[0] = (const float*)d_in[3];
    qkv.W[1] = Wrp + 1 * EMBD * EMBD; qkv.b[1] = (const float*)d_in[5];
    qkv.W[2] = Wrp + 2 * EMBD * EMBD; qkv.b[2] = (const float*)d_in[7];
    qkv.C[0] = Qp; qkv.C[1] = Kp; qkv.C[2] = Vp;
    const float* Wo = Wrp + 3 * EMBD * EMBD;
    const float* bo = (const float*)d_in[9];

    const int gemm_smem = 4 * GT * (int)sizeof(float);                  // 73728
    const int attn_smem = (8704 + 2 * 4352 * 2 + 128) * (int)sizeof(float); // 104960

    cudaFuncSetAttribute(gemm_qkv3, cudaFuncAttributeMaxDynamicSharedMemorySize,
                         gemm_smem);
    cudaFuncSetAttribute(gemm_out3, cudaFuncAttributeMaxDynamicSharedMemorySize,
                         gemm_smem);
    cudaFuncSetAttribute(attn_tc3, cudaFuncAttributeMaxDynamicSharedMemorySize,
                         attn_smem);
    // Ask for the maximum shared-memory carveout so two CTAs co-reside.
    cudaFuncSetAttribute(attn_tc3,
                         cudaFuncAttributePreferredSharedMemoryCarveout, 100);
    cudaFuncSetAttribute(gemm_qkv3,
                         cudaFuncAttributePreferredSharedMemoryCarveout, 100);
    cudaFuncSetAttribute(gemm_out3,
                         cudaFuncAttributePreferredSharedMemoryCarveout, 100);

    round_pass<<<512, 256>>>(ra);

    gemm_qkv3<<<dim3(EMBD / 128, SQ / 128, 3), 128, gemm_smem>>>(
        Xp, qkv, SQ, EMBD, EMBD);

    attn_tc3<<<dim3(SQ / 128, NHD), 128, attn_smem>>>(mask);

    gemm_out3<<<dim3(EMBD / 128, SQ / 128), 128, gemm_smem>>>(
        AOp, Wo, bo, out, SQ, EMBD, EMBD);
}